// round 1
// baseline (speedup 1.0000x reference)
#include <cuda_runtime.h>
#include <cuda_bf16.h>

// VoxelCollisionCost: B=1024, H=32, L=8 links, S=8 spheres, 256^3 SDF grid.
// One thread per (b,h,l). 8 lanes (l fastest) share one (b,h) -> shfl reduce.

#define GRID_N   256
#define N_LINKS  8
#define N_SPH    8

__global__ void __launch_bounds__(256) vox_cost_kernel(
    const float* __restrict__ link_pos,   // [B,H,8,3]
    const float* __restrict__ link_rot,   // [B,H,8,3,3]
    const float* __restrict__ sph_ctr,    // [8,8,3]
    const float* __restrict__ sph_rad,    // [8,8]
    const float* __restrict__ sdf,        // [256,256,256]
    const float* __restrict__ weight,     // [1]
    float* __restrict__ out)              // [B,H]
{
    __shared__ float s_ctr[N_LINKS * N_SPH * 3];   // 192
    __shared__ float s_rad[N_LINKS * N_SPH];       // 64
    __shared__ float s_stage[3072];                // 768 pos + 2304 rot floats

    const int tid = threadIdx.x;

    // Robot model -> smem (256 floats, one per thread)
    if (tid < 192) s_ctr[tid] = sph_ctr[tid];
    else           s_rad[tid - 192] = sph_rad[tid - 192];

    // Stage this block's 32 (b,h) poses via float4 (fully coalesced).
    // pos: 32*8*3 = 768 floats = 192 float4 ; rot: 32*8*9 = 2304 floats = 576 float4
    const float4* posv = reinterpret_cast<const float4*>(link_pos) + (size_t)blockIdx.x * 192;
    const float4* rotv = reinterpret_cast<const float4*>(link_rot) + (size_t)blockIdx.x * 576;
    float4* s4 = reinterpret_cast<float4*>(s_stage);
    #pragma unroll
    for (int k = 0; k < 3; k++) {
        int j = tid + k * 256;
        s4[j] = (j < 192) ? posv[j] : rotv[j - 192];
    }
    __syncthreads();

    const int lbh = tid >> 3;      // local (b,h) index within block: 0..31
    const int l   = tid & 7;       // link index

    // Conflict-free smem reads: bank = (8*(lane>>3) + 9*(lane&7)) mod 32 is a bijection.
    const float* R = s_stage + 768 + lbh * 72 + l * 9;
    const float* P = s_stage +       lbh * 24 + l * 3;
    const float r00 = R[0], r01 = R[1], r02 = R[2];
    const float r10 = R[3], r11 = R[4], r12 = R[5];
    const float r20 = R[6], r21 = R[7], r22 = R[8];
    const float px = P[0], py = P[1], pz = P[2];

    // Compute all 8 voxel indices first (independent gathers -> max MLP).
    int lin[N_SPH];
    #pragma unroll
    for (int s = 0; s < N_SPH; s++) {
        const float* c = s_ctr + (l * N_SPH + s) * 3;
        const float cx = c[0], cy = c[1], cz = c[2];
        const float x = fmaf(r00, cx, fmaf(r01, cy, fmaf(r02, cz, px)));
        const float y = fmaf(r10, cx, fmaf(r11, cy, fmaf(r12, cz, py)));
        const float z = fmaf(r20, cx, fmaf(r21, cy, fmaf(r22, cz, pz)));
        // exact reference semantics: floor((p - (-1.28)) / 0.01) with rn-division
        int ix = (int)floorf(__fdiv_rn(x + 1.28f, 0.01f));
        int iy = (int)floorf(__fdiv_rn(y + 1.28f, 0.01f));
        int iz = (int)floorf(__fdiv_rn(z + 1.28f, 0.01f));
        ix = min(max(ix, 0), GRID_N - 1);
        iy = min(max(iy, 0), GRID_N - 1);
        iz = min(max(iz, 0), GRID_N - 1);
        lin[s] = (ix << 16) | (iy << 8) | iz;
    }

    // Gather + penetration depth; separate loops so LDGs batch.
    float pen[N_SPH];
    #pragma unroll
    for (int s = 0; s < N_SPH; s++)
        pen[s] = s_rad[l * N_SPH + s] - __ldg(sdf + lin[s]);

    float m = pen[0];
    #pragma unroll
    for (int s = 1; s < N_SPH; s++) m = fmaxf(m, pen[s]);

    // threshold + clip + /0.25 (== *4 exactly)
    float res = fminf(fmaxf(m - 0.01f, 0.0f), 0.5f) * 4.0f;

    // sum over 8 links (lanes l..l+7 share (b,h))
    res += __shfl_xor_sync(0xffffffffu, res, 1);
    res += __shfl_xor_sync(0xffffffffu, res, 2);
    res += __shfl_xor_sync(0xffffffffu, res, 4);

    if (l == 0)
        out[(blockIdx.x << 5) | lbh] = weight[0] * res;
}

extern "C" void kernel_launch(void* const* d_in, const int* in_sizes, int n_in,
                              void* d_out, int out_size) {
    const float* link_pos = (const float*)d_in[0];
    const float* link_rot = (const float*)d_in[1];
    const float* sph_ctr  = (const float*)d_in[2];
    const float* sph_rad  = (const float*)d_in[3];
    const float* sdf      = (const float*)d_in[4];
    const float* weight   = (const float*)d_in[5];
    float* out = (float*)d_out;

    const int n_bh   = out_size;              // B*H = 32768
    const int blocks = (n_bh * N_LINKS) / 256; // 1024 blocks of 256 threads

    vox_cost_kernel<<<blocks, 256>>>(link_pos, link_rot, sph_ctr, sph_rad,
                                     sdf, weight, out);
}